// round 7
// baseline (speedup 1.0000x reference)
#include <cuda_runtime.h>
#include <math.h>

#define GRID 16
#define BLOCK 256
#define NTOT 4096
#define K2 (NTOT / BLOCK)   // 16 elements/thread in phase 2
#define NW (BLOCK / 32)     // 8 warps

// Persistent device state (reset by CTA0 at end of every launch).
__device__ unsigned long long g_Sc = 0ull, g_Ss = 0ull;
__device__ unsigned g_qmx = 0u, g_qmn = 0xffffffffu;
__device__ unsigned g_count = 0u;
__device__ float g_q[NTOT];
__device__ float g_cw[NTOT];

__device__ __forceinline__ float wsum_down(float x) {
#pragma unroll
    for (int o = 16; o > 0; o >>= 1) x += __shfl_down_sync(0xffffffffu, x, o);
    return x;
}
// Butterfly sum over 8 values replicated via sb[lane&7]; result in all lanes.
__device__ __forceinline__ float bfly8(float x) {
#pragma unroll
    for (int o = 4; o > 0; o >>= 1) x += __shfl_xor_sync(0xffffffffu, x, o);
    return x;
}
__device__ __forceinline__ unsigned redux_max_u32(unsigned v) {
    unsigned r;
    asm volatile("redux.sync.max.u32 %0, %1, 0xffffffff;" : "=r"(r) : "r"(v));
    return r;
}
__device__ __forceinline__ unsigned redux_min_u32(unsigned v) {
    unsigned r;
    asm volatile("redux.sync.min.u32 %0, %1, 0xffffffff;" : "=r"(r) : "r"(v));
    return r;
}

__global__ void __launch_bounds__(BLOCK, 1)
spectral_rank2_kernel(const float* __restrict__ in, float* __restrict__ out) {
    __shared__ float sA[NW], sB[NW], sC[NW];
    __shared__ unsigned sM[NW], sN[NW];
    __shared__ float cst[4];   // Sc, Ss, qmx, qmn broadcast

    const int t = threadIdx.x;
    const int lane = t & 31, w = t >> 5;
    const int cta = blockIdx.x;
    const int gid = cta * BLOCK + t;

    // ---- Phase 1 (all CTAs, spread over 16 SMs): feature transform.
    // sigmoid(|x|)=1/(1+e), v~=e, e=exp(-|x|); direction (1,q)/sqrt(1+q^2),
    // q = e + e^2 > 0.
    float x = in[gid];
    float e = __expf(-fabsf(x));
    float q1 = fmaf(e, e, e);
    float c1 = rsqrtf(fmaf(q1, q1, 1.f));
    g_q[gid] = q1;             // scratch for phase 2
    g_cw[gid] = c1;

    float pc = wsum_down(c1);
    float ps = wsum_down(q1 * c1);
    unsigned mq = redux_max_u32(__float_as_uint(q1));
    unsigned nq = redux_min_u32(__float_as_uint(q1));
    if (lane == 0) { sA[w] = pc; sB[w] = ps; sM[w] = mq; sN[w] = nq; }
    __threadfence();           // order scratch STGs (all threads) before arrival
    __syncthreads();

    if (w == 0) {
        float a = bfly8(sA[lane & 7]);
        float b = bfly8(sB[lane & 7]);
        unsigned m2 = redux_max_u32(sM[lane & 7]);
        unsigned n2 = redux_min_u32(sN[lane & 7]);
        if (lane == 0) {
            // Deterministic fixed-point accumulation (scale 2^32; per-CTA
            // partial <= 256 -> fits; total <= 2^44).
            atomicAdd(&g_Sc, (unsigned long long)llrintf(a * 4294967296.f));
            atomicAdd(&g_Ss, (unsigned long long)llrintf(b * 4294967296.f));
            atomicMax(&g_qmx, m2);
            atomicMin(&g_qmn, n2);
            __threadfence();   // sums visible before arrival tick
            atomicAdd(&g_count, 1u);
        }
    }
    if (cta != 0) return;      // producers done

    // ---- CTA0: wait for all 16 arrivals (single global sync).
    if (t == 0) {
        while (atomicAdd(&g_count, 0u) < GRID) __nanosleep(64);
        __threadfence();
        double sc = (double)g_Sc * 0x1p-32;
        double ss = (double)g_Ss * 0x1p-32;
        cst[0] = (float)sc;
        cst[1] = (float)ss;
        cst[2] = __uint_as_float(g_qmx);
        cst[3] = __uint_as_float(g_qmn);
        // Reset persistent state for the next graph replay (t0 is the only
        // reader of the raw values).
        g_Sc = 0ull; g_Ss = 0ull;
        g_qmx = 0u; g_qmn = 0xffffffffu; g_count = 0u;
    }
    __syncthreads();
    const float Sc = cst[0], Ss = cst[1], qmx = cst[2], qmn = cst[3];

    // ---- Phase 2 (CTA0 only): dis = rsqrt(degree), Gram partials.
    float qr[K2], cd[K2];
    float pa = 0.f, pb = 0.f, pg = 0.f;
#pragma unroll
    for (int k = 0; k < K2; k++) {
        int idx = t + k * BLOCK;           // coalesced
        float qq = g_q[idx];
        float c  = g_cw[idx];
        float d    = fmaf(qq, Ss, Sc) * c; // degree
        float cdis = c * rsqrtf(d);
        qr[k] = qq; cd[k] = cdis;
        float t2  = cdis * cdis;
        float t2q = t2 * qq;
        pa += t2;
        pb += t2q;
        pg = fmaf(t2q, qq, pg);
    }
    // One-barrier block reduction of the three Gram sums.
    {
        float a = wsum_down(pa);
        float b = wsum_down(pb);
        float g = wsum_down(pg);
        if (lane == 0) { sA[w] = a; sB[w] = b; sC[w] = g; }
    }
    __syncthreads();
    const float A = bfly8(sA[lane & 7]);
    const float B = bfly8(sB[lane & 7]);
    const float G = bfly8(sC[lane & 7]);

    // ---- Phase 3 (per-thread): 2x2 eigensolve, second eigenvalue.
    float diff = 0.5f * (A - G);
    float rr = sqrtf(fmaf(diff, diff, B * B));
    float al, be;
    if (diff >= 0.f) { al = B;         be = -(diff + rr); }
    else             { al = rr - diff; be = -B;            }

    // F monotone in q -> extremes at q_min/q_max; endpoints evaluated with the
    // exact per-element op sequence (bit-consistent).
    float Fe[2];
    float qe[2] = {qmn, qmx};
#pragma unroll
    for (int k = 0; k < 2; k++) {
        float c    = rsqrtf(fmaf(qe[k], qe[k], 1.f));
        float d    = fmaf(qe[k], Ss, Sc) * c;
        float cdis = c * rsqrtf(d);
        Fe[k] = fmaf(be, qe[k], al) * cdis;
    }
    float Fmn = fminf(Fe[0], Fe[1]);
    float Fmx = fmaxf(Fe[0], Fe[1]);
    float pivot = (fabsf(Fmx) >= fabsf(Fmn)) ? Fmx : Fmn;
    float sgn = (pivot >= 0.f) ? 1.f : -1.f;
    float mn = (sgn > 0.f) ? Fmn : -Fmx;
    float mx = (sgn > 0.f) ? Fmx : -Fmn;
    float scale = __fdividef(1.f, mx - mn + 1e-10f);
    float a1 = sgn * scale, a0 = -mn * scale;   // out = F*a1 + a0

    // ---- Phase 4: Fiedler values + fused normalize + store (all 4096).
#pragma unroll
    for (int k = 0; k < K2; k++) {
        int idx = t + k * BLOCK;
        float F = fmaf(be, qr[k], al) * cd[k];
        out[idx] = fmaf(F, a1, a0);
    }
}

extern "C" void kernel_launch(void* const* d_in, const int* in_sizes, int n_in,
                              void* d_out, int out_size) {
    (void)in_sizes; (void)n_in; (void)out_size;
    const float* in = (const float*)d_in[0];
    float* out = (float*)d_out;
    spectral_rank2_kernel<<<GRID, BLOCK>>>(in, out);
}

// round 8
// speedup vs baseline: 1.2651x; 1.2651x over previous
#include <cuda_runtime.h>
#include <math.h>

#define BLOCK 512
#define K 8
#define NW (BLOCK / 32)      // 16 warps

// Warp sum, result in lane 0 (shfl_down chain).
__device__ __forceinline__ float wsum_down(float x) {
#pragma unroll
    for (int o = 16; o > 0; o >>= 1) x += __shfl_down_sync(0xffffffffu, x, o);
    return x;
}
// Butterfly sum over the 16 warp partials (replicated x2 across the warp);
// result in all lanes.
__device__ __forceinline__ float bfly16(float x) {
#pragma unroll
    for (int o = 8; o > 0; o >>= 1) x += __shfl_xor_sync(0xffffffffu, x, o);
    return x;
}
// Integer REDUX (sm_103). Positive-float bit patterns are order-isomorphic
// to u32, so these give float min/max for q > 0.
__device__ __forceinline__ unsigned redux_max_u32(unsigned v) {
    unsigned r;
    asm volatile("redux.sync.max.u32 %0, %1, 0xffffffff;" : "=r"(r) : "r"(v));
    return r;
}
__device__ __forceinline__ unsigned redux_min_u32(unsigned v) {
    unsigned r;
    asm volatile("redux.sync.min.u32 %0, %1, 0xffffffff;" : "=r"(r) : "r"(v));
    return r;
}

__global__ void __launch_bounds__(BLOCK, 1)
spectral_rank2_kernel(const float4* __restrict__ in4, float4* __restrict__ out4) {
    __shared__ float sb1[2][NW];
    __shared__ unsigned sq[2][NW];
    __shared__ float sb2[3][NW];
    const int t = threadIdx.x;
    const int lane = t & 31, w = t >> 5;

    // ---- Phase 1: load (2 x float4, MLP=2) + feature transform.
    // sigmoid(|x|)=1/(1+e), v~=e, e=exp(-|x|); direction (1,q)/sqrt(1+q^2),
    // q = e + e^2 > 0.
    float4 xa = in4[t];
    float4 xb = in4[t + BLOCK];
    float xs[K] = {xa.x, xa.y, xa.z, xa.w, xb.x, xb.y, xb.z, xb.w};
    float q[K], cw[K];
    float pc = 0.f, ps = 0.f;
    unsigned pqmx = 0u, pqmn = 0xffffffffu;
#pragma unroll
    for (int k = 0; k < K; k++) {
        float e  = __expf(-fabsf(xs[k]));
        float qq = fmaf(e, e, e);                  // q = e + e^2
        float c  = rsqrtf(fmaf(qq, qq, 1.f));
        q[k] = qq; cw[k] = c;
        pc += c;
        ps = fmaf(qq, c, ps);
        unsigned qb = __float_as_uint(qq);
        pqmx = max(pqmx, qb);
        pqmn = min(pqmn, qb);
    }
    // ---- R1: one barrier, two levels.
    {
        float a = wsum_down(pc);
        float b = wsum_down(ps);
        unsigned m = redux_max_u32(pqmx);
        unsigned n = redux_min_u32(pqmn);
        if (lane == 0) { sb1[0][w] = a; sb1[1][w] = b; sq[0][w] = m; sq[1][w] = n; }
    }
    __syncthreads();
    const float Sc = bfly16(sb1[0][lane & 15]);
    const float Ss = bfly16(sb1[1][lane & 15]);
    const float qmx = __uint_as_float(redux_max_u32(sq[0][lane & 15]));
    const float qmn = __uint_as_float(redux_min_u32(sq[1][lane & 15]));

    // ---- Phase 2: dis = rsqrt(degree); cdis = c*dis; Gram partials.
    // u = cdis, v = q*cdis; A=sum u^2, B=sum uv, G=sum v^2.
    float cd[K];
    float pa = 0.f, pb = 0.f, pg = 0.f;
#pragma unroll
    for (int k = 0; k < K; k++) {
        float d    = fmaf(q[k], Ss, Sc) * cw[k];   // degree
        float cdis = cw[k] * rsqrtf(d);
        cd[k] = cdis;
        float t2  = cdis * cdis;
        float t2q = t2 * q[k];
        pa += t2;
        pb += t2q;
        pg = fmaf(t2q, q[k], pg);
    }
    // ---- R2: one barrier, two levels.
    {
        float a = wsum_down(pa);
        float b = wsum_down(pb);
        float g = wsum_down(pg);
        if (lane == 0) { sb2[0][w] = a; sb2[1][w] = b; sb2[2][w] = g; }
    }
    __syncthreads();
    const float A = bfly16(sb2[0][lane & 15]);
    const float B = bfly16(sb2[1][lane & 15]);
    const float G = bfly16(sb2[2][lane & 15]);

    // ---- Phase 3 (per-thread, no barrier): 2x2 eigensolve, second eigenvalue.
    float diff = 0.5f * (A - G);
    float rr = sqrtf(fmaf(diff, diff, B * B));
    float al, be;
    if (diff >= 0.f) { al = B;         be = -(diff + rr); }
    else             { al = rr - diff; be = -B;            }

    // F monotone in q -> extremes at q_min/q_max; endpoints evaluated with
    // the EXACT per-element op sequence (bit-consistent min/max).
    float Fe[2];
    float qe[2] = {qmn, qmx};
#pragma unroll
    for (int k = 0; k < 2; k++) {
        float c    = rsqrtf(fmaf(qe[k], qe[k], 1.f));
        float d    = fmaf(qe[k], Ss, Sc) * c;
        float cdis = c * rsqrtf(d);
        Fe[k] = fmaf(be, qe[k], al) * cdis;
    }
    float Fmn = fminf(Fe[0], Fe[1]);
    float Fmx = fmaxf(Fe[0], Fe[1]);
    float pivot = (fabsf(Fmx) >= fabsf(Fmn)) ? Fmx : Fmn;
    float sgn = (pivot >= 0.f) ? 1.f : -1.f;
    float mn = (sgn > 0.f) ? Fmn : -Fmx;
    float mx = (sgn > 0.f) ? Fmx : -Fmn;
    float scale = __fdividef(1.f, mx - mn + 1e-10f);
    float a1 = sgn * scale, a0 = -mn * scale;   // out = F*a1 + a0

    // ---- Phase 4: Fiedler values + fused normalize + store (2 x float4).
    float r[K];
#pragma unroll
    for (int k = 0; k < K; k++)
        r[k] = fmaf(fmaf(be, q[k], al) * cd[k], a1, a0);
    out4[t]         = make_float4(r[0], r[1], r[2], r[3]);
    out4[t + BLOCK] = make_float4(r[4], r[5], r[6], r[7]);
}

extern "C" void kernel_launch(void* const* d_in, const int* in_sizes, int n_in,
                              void* d_out, int out_size) {
    (void)in_sizes; (void)n_in; (void)out_size;
    const float4* in = (const float4*)d_in[0];
    float4* out = (float4*)d_out;
    spectral_rank2_kernel<<<1, BLOCK>>>(in, out);
}

// round 9
// speedup vs baseline: 1.3077x; 1.0337x over previous
#include <cuda_runtime.h>
#include <math.h>

#define BLOCK 512
#define K 8
#define NW (BLOCK / 32)      // 16 warps

// Warp sum, result in lane 0 (shfl_down chain).
__device__ __forceinline__ float wsum_down(float x) {
#pragma unroll
    for (int o = 16; o > 0; o >>= 1) x += __shfl_down_sync(0xffffffffu, x, o);
    return x;
}
// Butterfly sum over the 16 warp partials (replicated x2 across the warp);
// result in all lanes.
__device__ __forceinline__ float bfly16(float x) {
#pragma unroll
    for (int o = 8; o > 0; o >>= 1) x += __shfl_xor_sync(0xffffffffu, x, o);
    return x;
}
// Integer REDUX (sm_103). Positive-float bit patterns are order-isomorphic
// to u32, so these give float min/max for q > 0.
__device__ __forceinline__ unsigned redux_max_u32(unsigned v) {
    unsigned r;
    asm volatile("redux.sync.max.u32 %0, %1, 0xffffffff;" : "=r"(r) : "r"(v));
    return r;
}
__device__ __forceinline__ unsigned redux_min_u32(unsigned v) {
    unsigned r;
    asm volatile("redux.sync.min.u32 %0, %1, 0xffffffff;" : "=r"(r) : "r"(v));
    return r;
}

__global__ void __launch_bounds__(BLOCK, 1)
spectral_rank2_kernel(const float4* __restrict__ in4, float4* __restrict__ out4) {
    __shared__ float sb1[2][NW];
    __shared__ unsigned sq[2][NW];
    const int t = threadIdx.x;
    const int lane = t & 31, w = t >> 5;

    // ---- Phase 1: load (2 x float4, MLP=2) + feature transform.
    // sigmoid(|x|)=1/(1+e), v~=e, e=exp(-|x|); direction (1,q)/sqrt(1+q^2),
    // q = e + e^2 > 0.
    float4 xa = in4[t];
    float4 xb = in4[t + BLOCK];
    float xs[K] = {xa.x, xa.y, xa.z, xa.w, xb.x, xb.y, xb.z, xb.w};
    float q[K], cw[K];
    float pc = 0.f, ps = 0.f;
    unsigned pqmx = 0u, pqmn = 0xffffffffu;
#pragma unroll
    for (int k = 0; k < K; k++) {
        float e  = __expf(-fabsf(xs[k]));
        float qq = fmaf(e, e, e);                  // q = e + e^2
        float c  = rsqrtf(fmaf(qq, qq, 1.f));
        q[k] = qq; cw[k] = c;
        pc += c;
        ps = fmaf(qq, c, ps);
        unsigned qb = __float_as_uint(qq);
        pqmx = max(pqmx, qb);
        pqmn = min(pqmn, qb);
    }
    // ---- R1 (the ONLY reduction round): Sc, Ss sums + q extremes.
    {
        float a = wsum_down(pc);
        float b = wsum_down(ps);
        unsigned m = redux_max_u32(pqmx);
        unsigned n = redux_min_u32(pqmn);
        if (lane == 0) { sb1[0][w] = a; sb1[1][w] = b; sq[0][w] = m; sq[1][w] = n; }
    }
    __syncthreads();
    const float Sc = bfly16(sb1[0][lane & 15]);
    const float Ss = bfly16(sb1[1][lane & 15]);
    const float qmx = __uint_as_float(redux_max_u32(sq[0][lane & 15]));
    const float qmn = __uint_as_float(redux_min_u32(sq[1][lane & 15]));

    // ---- Phase 2 (no further reductions needed):
    // The rank-2 Gram matrix has Perron eigenvector exactly (Sc, Ss)
    // (identity: A*Sc + B*Ss = Sc, B*Sc + G*Ss = Ss), so the Fiedler
    // direction is its orthogonal complement: (al, be) = (-Ss, Sc).
    // F(q) ∝ sin(θ-φ)/sqrt(cos(θ-φ)), θ=atan q — strictly increasing in q,
    // so min/max are at qmn/qmx (evaluated with the identical op sequence).
    const float al = -Ss, be = Sc;

    float Fe[2];
    float qe[2] = {qmn, qmx};
#pragma unroll
    for (int k = 0; k < 2; k++) {
        float c    = rsqrtf(fmaf(qe[k], qe[k], 1.f));
        float d    = fmaf(qe[k], Ss, Sc) * c;
        float cdis = c * rsqrtf(d);
        Fe[k] = fmaf(be, qe[k], al) * cdis;
    }
    float Fmn = Fe[0], Fmx = Fe[1];              // monotone increasing
    float pivot = (fabsf(Fmx) >= fabsf(Fmn)) ? Fmx : Fmn;
    float sgn = (pivot >= 0.f) ? 1.f : -1.f;
    float mn = (sgn > 0.f) ? Fmn : -Fmx;
    float mx = (sgn > 0.f) ? Fmx : -Fmn;
    float scale = __fdividef(1.f, mx - mn + 1e-10f);
    float a1 = sgn * scale, a0 = -mn * scale;    // out = F*a1 + a0

    // ---- Phase 3: per-element Fiedler value + fused normalize + store.
    float r[K];
#pragma unroll
    for (int k = 0; k < K; k++) {
        float d    = fmaf(q[k], Ss, Sc) * cw[k];  // degree
        float cdis = cw[k] * rsqrtf(d);
        float F    = fmaf(be, q[k], al) * cdis;
        r[k] = fmaf(F, a1, a0);
    }
    out4[t]         = make_float4(r[0], r[1], r[2], r[3]);
    out4[t + BLOCK] = make_float4(r[4], r[5], r[6], r[7]);
}

extern "C" void kernel_launch(void* const* d_in, const int* in_sizes, int n_in,
                              void* d_out, int out_size) {
    (void)in_sizes; (void)n_in; (void)out_size;
    const float4* in = (const float4*)d_in[0];
    float4* out = (float4*)d_out;
    spectral_rank2_kernel<<<1, BLOCK>>>(in, out);
}